// round 2
// baseline (speedup 1.0000x reference)
#include <cuda_runtime.h>
#include <cuda_bf16.h>
#include <cstdint>
#include <cmath>

#define T_LEN 1024
#define NH    512
#define NI    128
#define BSZ   64
#define DT_C  0.1f

// Hoisted input projection scratch: tanh(x @ x2h), [B, T, H] fp32 (134 MB).
__device__ float g_tanhI[(size_t)BSZ * T_LEN * NH];

// ---------------------------------------------------------------------------
// helpers
// ---------------------------------------------------------------------------
__device__ __forceinline__ uint32_t smem_u32(const void* p) {
    uint32_t a;
    asm("{ .reg .u64 t; cvta.to.shared.u64 t, %1; cvt.u32.u64 %0, t; }" : "=r"(a) : "l"(p));
    return a;
}
__device__ __forceinline__ uint32_t mapa_sc(uint32_t addr, uint32_t rank) {
    uint32_t r;
    asm("mapa.shared::cluster.u32 %0, %1, %2;" : "=r"(r) : "r"(addr), "r"(rank));
    return r;
}
__device__ __forceinline__ void st_sc_f32(uint32_t addr, float v) {
    asm volatile("st.shared::cluster.f32 [%0], %1;" :: "r"(addr), "f"(v) : "memory");
}
__device__ __forceinline__ void cluster_sync_() {
    asm volatile("barrier.cluster.arrive.aligned;" ::: "memory");
    asm volatile("barrier.cluster.wait.aligned;" ::: "memory");
}

// ---------------------------------------------------------------------------
// Phase 1: g_tanhI[bt, h] = tanh( x[bt, :] @ x2h[:, h] ), bt in [0, B*T).
// CTA: 16 rows x 512 cols, K=128. 256 threads.
// ---------------------------------------------------------------------------
__global__ void __launch_bounds__(256) phase1_kernel(const float* __restrict__ x,
                                                     const float* __restrict__ x2h) {
    __shared__ float  x_s[16 * 132];
    __shared__ float4 w4_s[128 * 16];   // 128 k x 64 cols (as 16 float4)
    const int tid = threadIdx.x;
    const int bt0 = blockIdx.x * 16;

    // load 16x128 x tile (512 float4)
    for (int i = tid; i < 512; i += 256) {
        int r = i >> 5, c = i & 31;
        float4 v = *reinterpret_cast<const float4*>(x + (size_t)(bt0 + r) * NI + c * 4);
        *reinterpret_cast<float4*>(x_s + r * 132 + c * 4) = v;
    }

    const int tt = tid & 15;   // row in tile
    const int jc = tid >> 4;   // col group (4 cols)
    for (int chunk = 0; chunk < 8; ++chunk) {
        __syncthreads();
        const int jbase = chunk * 64;
        for (int i = tid; i < 2048; i += 256) {      // 128 x 16 float4
            int k = i >> 4, jq = i & 15;
            w4_s[k * 16 + jq] =
                *reinterpret_cast<const float4*>(x2h + (size_t)k * NH + jbase + jq * 4);
        }
        __syncthreads();
        float a0 = 0.f, a1 = 0.f, a2 = 0.f, a3 = 0.f;
        #pragma unroll 8
        for (int k = 0; k < 128; ++k) {
            float  xv = x_s[tt * 132 + k];
            float4 w  = w4_s[k * 16 + jc];
            a0 = fmaf(xv, w.x, a0); a1 = fmaf(xv, w.y, a1);
            a2 = fmaf(xv, w.z, a2); a3 = fmaf(xv, w.w, a3);
        }
        float4 o = make_float4(tanhf(a0), tanhf(a1), tanhf(a2), tanhf(a3));
        *reinterpret_cast<float4*>(g_tanhI + (size_t)(bt0 + tt) * NH + jbase + jc * 4) = o;
    }
}

// ---------------------------------------------------------------------------
// Phase 2: recurrence. 16 clusters x 8 CTAs x 256 threads.
// Cluster c owns batch rows [4c, 4c+4). CTA rank owns hidden cols
// J = [64*rank, 64*rank+64), weight slice resident transposed in SMEM:
//   wT[jl][k] = h2h[k][J0+jl], row stride 513 floats.
// SMEM float layout (dynamic):
//   [0)            wT        64*513  = 32832
//   [32832)        hy4       512 float4 (hy[m][k], m packed)   2048
//   [34880)        pre4      64 float4                          256
//   [35136)        stage     4*64 float4 (GEMM1 k-split)       1024
//   [36160)        red       8 src * 4 m * 64 kl               2048
//   [38208)        bias_s    64
//   total 38272 floats = 153088 B
// ---------------------------------------------------------------------------
#define W_OFF     0
#define HY_OFF    32832
#define PRE_OFF   34880
#define STG_OFF   35136
#define RED_OFF   36160
#define BIAS_OFF  38208
#define SMEM_FLOATS 38272
#define SMEM_BYTES  (SMEM_FLOATS * 4)
#define WSTRIDE   513

__global__ void __launch_bounds__(256)
rnn_kernel(const float* __restrict__ h2h, const float* __restrict__ bias,
           const float* __restrict__ gamma_v, const float* __restrict__ eps_v,
           float* __restrict__ out_states, float* __restrict__ out_hy) {
    extern __shared__ float sm[];
    float*  wT_s   = sm + W_OFF;
    float4* hy4_s  = reinterpret_cast<float4*>(sm + HY_OFF);
    float4* pre4_s = reinterpret_cast<float4*>(sm + PRE_OFF);
    float4* stg4_s = reinterpret_cast<float4*>(sm + STG_OFF);
    float*  red_s  = sm + RED_OFF;
    float*  bias_s = sm + BIAS_OFF;

    const int tid = threadIdx.x;
    uint32_t rank;
    asm("mov.u32 %0, %%cluster_ctarank;" : "=r"(rank));
    const int m_base = (blockIdx.x >> 3) * 4;    // 4 batch rows per cluster
    const int J0 = (int)rank * 64;

    const uint32_t smb = smem_u32(sm);

    // --- init: load weight slice (transposed), bias, zero hy ---
    for (int idx = tid; idx < 64 * 512; idx += 256) {
        int k = idx >> 6, jl = idx & 63;
        wT_s[jl * WSTRIDE + k] = h2h[(size_t)k * NH + J0 + jl];
    }
    if (tid < 64) bias_s[tid] = bias[J0 + tid];
    for (int i = tid; i < 512; i += 256) hy4_s[i] = make_float4(0.f, 0.f, 0.f, 0.f);
    __syncthreads();
    cluster_sync_();

    // GEMM1 thread mapping: tid = ks*64 + jg  (ks in 0..3 k-split, jg = local j)
    const int ks = tid >> 6;
    const int jg = tid & 63;
    // GEMM2 thread mapping: k0 = tid, k1 = tid + 256
    const int k0 = tid, k1 = tid + 256;
    const int kl02 = k0 & 63;           // same for k1
    const uint32_t r0 = (uint32_t)(k0 >> 6), r1 = r0 + 4;
    // update mapping: tid = m_u*64 + kl_u ; this thread owns (m_u, k_own)
    const int m_u = tid >> 6;
    const int kl_u = tid & 63;
    const int k_own = (int)rank * 64 + kl_u;

    // hoisted remote bases
    const uint32_t red_base_r0 = mapa_sc(smb + RED_OFF * 4, r0);
    const uint32_t red_base_r1 = mapa_sc(smb + RED_OFF * 4, r1);
    uint32_t hy_base[8];
    #pragma unroll
    for (int r = 0; r < 8; ++r) hy_base[r] = mapa_sc(smb + HY_OFF * 4, (uint32_t)r);

    float hy_r = 0.f, hz_r = 0.f;
    const float g_r = gamma_v[k_own];
    const float e_r = eps_v[k_own];
    const size_t row_base = (size_t)(m_base + m_u) * T_LEN * NH + k_own;
    float tI = g_tanhI[row_base];   // t = 0 prefetch

    for (int t = 0; t < T_LEN; ++t) {
        // ---- GEMM1 partial: pre_part[m, jg] over k in [ks*128, ks*128+128) ----
        {
            float a0 = 0.f, a1 = 0.f, a2 = 0.f, a3 = 0.f;
            const float* wcol = wT_s + jg * WSTRIDE + ks * 128;
            const float4* hyk = hy4_s + ks * 128;
            #pragma unroll 8
            for (int k = 0; k < 128; ++k) {
                float  w = wcol[k];
                float4 h = hyk[k];
                a0 = fmaf(w, h.x, a0); a1 = fmaf(w, h.y, a1);
                a2 = fmaf(w, h.z, a2); a3 = fmaf(w, h.w, a3);
            }
            stg4_s[ks * 64 + jg] = make_float4(a0, a1, a2, a3);
        }
        __syncthreads();
        if (tid < 64) {
            float4 s0 = stg4_s[tid], s1 = stg4_s[64 + tid];
            float4 s2 = stg4_s[128 + tid], s3 = stg4_s[192 + tid];
            float b = bias_s[tid];
            float4 p;
            p.x = tanhf(s0.x + s1.x + s2.x + s3.x + b);
            p.y = tanhf(s0.y + s1.y + s2.y + s3.y + b);
            p.z = tanhf(s0.z + s1.z + s2.z + s3.z + b);
            p.w = tanhf(s0.w + s1.w + s2.w + s3.w + b);
            pre4_s[tid] = p;
        }
        __syncthreads();

        // ---- GEMM2 partial: part[m, k] = sum_{jl} pre[m,jl] * wT[jl][k] ----
        float4 acc0 = make_float4(0.f, 0.f, 0.f, 0.f);
        float4 acc1 = make_float4(0.f, 0.f, 0.f, 0.f);
        #pragma unroll 8
        for (int j = 0; j < 64; ++j) {
            float4 p = pre4_s[j];
            float w0 = wT_s[j * WSTRIDE + k0];
            float w1 = wT_s[j * WSTRIDE + k1];
            acc0.x = fmaf(w0, p.x, acc0.x); acc0.y = fmaf(w0, p.y, acc0.y);
            acc0.z = fmaf(w0, p.z, acc0.z); acc0.w = fmaf(w0, p.w, acc0.w);
            acc1.x = fmaf(w1, p.x, acc1.x); acc1.y = fmaf(w1, p.y, acc1.y);
            acc1.z = fmaf(w1, p.z, acc1.z); acc1.w = fmaf(w1, p.w, acc1.w);
        }
        // scatter partials to k-owners: red[srcrank][m][kl]
        {
            uint32_t o0 = red_base_r0 + (uint32_t)((rank * 256 + kl02) * 4);
            uint32_t o1 = red_base_r1 + (uint32_t)((rank * 256 + kl02) * 4);
            st_sc_f32(o0,              acc0.x);
            st_sc_f32(o0 + 64 * 4,     acc0.y);
            st_sc_f32(o0 + 128 * 4,    acc0.z);
            st_sc_f32(o0 + 192 * 4,    acc0.w);
            st_sc_f32(o1,              acc1.x);
            st_sc_f32(o1 + 64 * 4,     acc1.y);
            st_sc_f32(o1 + 128 * 4,    acc1.z);
            st_sc_f32(o1 + 192 * 4,    acc1.w);
        }
        cluster_sync_();   // partials visible

        // ---- owner reduce + state update for (m_u, k_own) ----
        // prefetch next-step tanhI early (consumed next iteration)
        int tn = (t + 1 < T_LEN) ? (t + 1) : (T_LEN - 1);
        float tI_next = g_tanhI[row_base + (size_t)tn * NH];

        float s = 0.f;
        #pragma unroll
        for (int src = 0; src < 8; ++src)
            s += red_s[src * 256 + m_u * 64 + kl_u];

        hz_r = hz_r + DT_C * (tI - s - g_r * hy_r - e_r * hz_r);
        hy_r = hy_r + DT_C * hz_r;
        tI = tI_next;

        if (out_states)
            out_states[(size_t)(m_base + m_u) * T_LEN * NH + (size_t)t * NH + k_own] = hy_r;

        // broadcast new hy to all 8 CTAs' hy4_s[k_own].m
        {
            uint32_t off = (uint32_t)((k_own * 4 + m_u) * 4);
            #pragma unroll
            for (int r = 0; r < 8; ++r)
                st_sc_f32(hy_base[r] + off, hy_r);
        }
        cluster_sync_();   // hy visible for next GEMM1
    }

    if (out_hy)
        out_hy[(size_t)(m_base + m_u) * NH + k_own] = hy_r;
}

// ---------------------------------------------------------------------------
extern "C" void kernel_launch(void* const* d_in, const int* in_sizes, int n_in,
                              void* d_out, int out_size) {
    const float* x     = (const float*)d_in[0];
    const float* x2h   = (const float*)d_in[1];
    const float* h2h   = (const float*)d_in[2];
    const float* bias  = (const float*)d_in[3];
    const float* gam   = (const float*)d_in[4];
    const float* eps   = (const float*)d_in[5];
    float* out = (float*)d_out;

    const long long BTH = (long long)BSZ * T_LEN * NH;   // 33554432
    float* states = nullptr;
    float* hyout  = nullptr;
    if ((long long)out_size >= BTH) {
        states = out;
        if ((long long)out_size >= BTH + (long long)BSZ * NH) hyout = out + BTH;
    } else {
        hyout = out;   // output is just the final hy
    }

    phase1_kernel<<<(BSZ * T_LEN) / 16, 256>>>(x, x2h);

    cudaFuncSetAttribute(rnn_kernel, cudaFuncAttributeMaxDynamicSharedMemorySize,
                         SMEM_BYTES);

    cudaLaunchConfig_t cfg = {};
    cfg.gridDim = dim3(128, 1, 1);
    cfg.blockDim = dim3(256, 1, 1);
    cfg.dynamicSmemBytes = SMEM_BYTES;
    cfg.stream = 0;
    cudaLaunchAttribute attrs[1];
    attrs[0].id = cudaLaunchAttributeClusterDimension;
    attrs[0].val.clusterDim.x = 8;
    attrs[0].val.clusterDim.y = 1;
    attrs[0].val.clusterDim.z = 1;
    cfg.attrs = attrs;
    cfg.numAttrs = 1;
    cudaLaunchKernelEx(&cfg, rnn_kernel, h2h, bias, gam, eps, states, hyout);
}

// round 3
// speedup vs baseline: 1.3187x; 1.3187x over previous
#include <cuda_runtime.h>
#include <cuda_bf16.h>
#include <cstdint>
#include <cmath>

#define T_LEN 1024
#define NH    512
#define NI    128
#define BSZ   64
#define DT_C  0.1f

// Hoisted input projection scratch: tanh(x @ x2h), [B, T, H] fp32 (134 MB).
__device__ float g_tanhI[(size_t)BSZ * T_LEN * NH];

// ---------------------------------------------------------------------------
// helpers
// ---------------------------------------------------------------------------
__device__ __forceinline__ uint32_t smem_u32(const void* p) {
    uint32_t a;
    asm("{ .reg .u64 t; cvta.to.shared.u64 t, %1; cvt.u32.u64 %0, t; }" : "=r"(a) : "l"(p));
    return a;
}
__device__ __forceinline__ uint32_t mapa_sc(uint32_t addr, uint32_t rank) {
    uint32_t r;
    asm("mapa.shared::cluster.u32 %0, %1, %2;" : "=r"(r) : "r"(addr), "r"(rank));
    return r;
}
__device__ __forceinline__ void st_dsm_v2(uint32_t addr, unsigned long long a,
                                          unsigned long long b) {
    asm volatile("st.shared::cluster.v2.b64 [%0], {%1, %2};"
                 :: "r"(addr), "l"(a), "l"(b) : "memory");
}
__device__ __forceinline__ void cluster_sync_() {
    asm volatile("barrier.cluster.arrive.aligned;" ::: "memory");
    asm volatile("barrier.cluster.wait.aligned;" ::: "memory");
}
// packed fp32x2: d = a*b + d  (SASS FFMA2 path)
__device__ __forceinline__ unsigned long long pack2(float w) {
    unsigned long long r;
    asm("mov.b64 %0, {%1, %1};" : "=l"(r) : "f"(w));
    return r;
}
__device__ __forceinline__ void ffma2(unsigned long long& d, unsigned long long a,
                                      unsigned long long b) {
    asm("fma.rn.f32x2 %0, %1, %2, %0;" : "+l"(d) : "l"(a), "l"(b));
}

// ---------------------------------------------------------------------------
// Phase 1: g_tanhI[bt, h] = tanh( x[bt, :] @ x2h[:, h] ), bt in [0, B*T).
// ---------------------------------------------------------------------------
__global__ void __launch_bounds__(256) phase1_kernel(const float* __restrict__ x,
                                                     const float* __restrict__ x2h) {
    __shared__ float  x_s[16 * 132];
    __shared__ float4 w4_s[128 * 16];
    const int tid = threadIdx.x;
    const int bt0 = blockIdx.x * 16;

    for (int i = tid; i < 512; i += 256) {
        int r = i >> 5, c = i & 31;
        float4 v = *reinterpret_cast<const float4*>(x + (size_t)(bt0 + r) * NI + c * 4);
        *reinterpret_cast<float4*>(x_s + r * 132 + c * 4) = v;
    }

    const int tt = tid & 15;
    const int jc = tid >> 4;
    for (int chunk = 0; chunk < 8; ++chunk) {
        __syncthreads();
        const int jbase = chunk * 64;
        for (int i = tid; i < 2048; i += 256) {
            int k = i >> 4, jq = i & 15;
            w4_s[k * 16 + jq] =
                *reinterpret_cast<const float4*>(x2h + (size_t)k * NH + jbase + jq * 4);
        }
        __syncthreads();
        float a0 = 0.f, a1 = 0.f, a2 = 0.f, a3 = 0.f;
        #pragma unroll 8
        for (int k = 0; k < 128; ++k) {
            float  xv = x_s[tt * 132 + k];
            float4 w  = w4_s[k * 16 + jc];
            a0 = fmaf(xv, w.x, a0); a1 = fmaf(xv, w.y, a1);
            a2 = fmaf(xv, w.z, a2); a3 = fmaf(xv, w.w, a3);
        }
        float4 o = make_float4(tanhf(a0), tanhf(a1), tanhf(a2), tanhf(a3));
        *reinterpret_cast<float4*>(g_tanhI + (size_t)(bt0 + tt) * NH + jbase + jc * 4) = o;
    }
}

// ---------------------------------------------------------------------------
// Phase 2: recurrence. 16 clusters x 8 CTAs x 512 threads.
// Cluster owns 4 batch rows; CTA rank owns hidden cols J=[64r, 64r+64) with
// its h2h column-slice resident transposed in SMEM: wT[jl][k], stride 513.
//
// SMEM float layout:
//   [0)      wT       64*513 = 32832
//   [32832)  hy4      512*4   (hy[k][m])
//   [34880)  pre      64*4    (pre[j][m])
//   [35136)  stage    8*64*4  (GEMM1 k-split partials [ks][j][m])
//   [37184)  red      8*64*4  (GEMM2 partials [src][kl][m])
//   [39232)  hystage  64*4    ([kl][m])
//   [39488)  bias     64
//   total 39552 floats = 158208 B
// ---------------------------------------------------------------------------
#define W_OFF     0
#define HY_OFF    32832
#define PRE_OFF   34880
#define STG_OFF   35136
#define RED_OFF   37184
#define HYST_OFF  39232
#define BIAS_OFF  39488
#define SMEM_FLOATS 39552
#define SMEM_BYTES  (SMEM_FLOATS * 4)
#define WSTRIDE   513

__global__ void __launch_bounds__(512)
rnn_kernel(const float* __restrict__ h2h, const float* __restrict__ bias,
           const float* __restrict__ gamma_v, const float* __restrict__ eps_v,
           float* __restrict__ out_states, float* __restrict__ out_hy) {
    extern __shared__ float sm[];
    float* wT_s   = sm + W_OFF;
    float* bias_s = sm + BIAS_OFF;

    const int tid = threadIdx.x;
    uint32_t rank;
    asm("mov.u32 %0, %%cluster_ctarank;" : "=r"(rank));
    const int m_base = (blockIdx.x >> 3) * 4;
    const int J0 = (int)rank * 64;
    const uint32_t smb = smem_u32(sm);

    // --- init: weight slice (transposed), bias, zero hy ---
    for (int idx = tid; idx < 64 * 512; idx += 512) {
        int k = idx >> 6, jl = idx & 63;
        wT_s[jl * WSTRIDE + k] = h2h[(size_t)k * NH + J0 + jl];
    }
    if (tid < 64) bias_s[tid] = bias[J0 + tid];
    for (int i = tid; i < 2048; i += 512) sm[HY_OFF + i] = 0.f;

    // --- fixed thread mappings ---
    const int ks = tid >> 6;          // GEMM1 k-split 0..7
    const int jg = tid & 63;          // GEMM1 local j
    const int k2 = tid;               // GEMM2 k (0..511)
    // update mapping (tid < 256): kl = tid>>2, m = tid&3
    const int kl_u = tid >> 2;
    const int m_u  = tid & 3;
    const int k_own = J0 + kl_u;

    // hoisted DSMEM addresses
    const uint32_t red_dst = mapa_sc(smb + RED_OFF * 4, (uint32_t)(k2 >> 6)) +
                             (uint32_t)((rank * 256 + (k2 & 63) * 4) * 4);
    const uint32_t hy_dst  = mapa_sc(smb + HY_OFF * 4, (uint32_t)(tid >> 6)) +
                             (uint32_t)((J0 + (tid & 63)) * 16);

    float hy_r = 0.f, hz_r = 0.f, g_r = 0.f, e_r = 0.f, tI = 0.f;
    size_t row_base = 0;
    if (tid < 256) {
        g_r = gamma_v[k_own];
        e_r = eps_v[k_own];
        row_base = (size_t)(m_base + m_u) * T_LEN * NH + k_own;
        tI = g_tanhI[row_base];
    }

    __syncthreads();
    cluster_sync_();

    const float* wcol = wT_s + jg * WSTRIDE + ks * 64;
    const ulonglong2* hyk  = reinterpret_cast<const ulonglong2*>(sm + HY_OFF) + ks * 64;
    const ulonglong2* pre2 = reinterpret_cast<const ulonglong2*>(sm + PRE_OFF);
    ulonglong2* stg2 = reinterpret_cast<ulonglong2*>(sm + STG_OFF);

    for (int t = 0; t < T_LEN; ++t) {
        // ---- GEMM1 k-split partial: pre_part[ks][jg][m] ----
        {
            unsigned long long a01 = 0ull, a23 = 0ull;
            #pragma unroll 16
            for (int k = 0; k < 64; ++k) {
                unsigned long long w2 = pack2(wcol[k]);
                ulonglong2 h = hyk[k];
                ffma2(a01, w2, h.x);
                ffma2(a23, w2, h.y);
            }
            stg2[ks * 64 + jg] = make_ulonglong2(a01, a23);
        }
        __syncthreads();
        if (tid < 256) {                 // sum 8 partials + bias + tanh
            float s = bias_s[tid >> 2];
            #pragma unroll
            for (int q = 0; q < 8; ++q) s += sm[STG_OFF + q * 256 + tid];
            sm[PRE_OFF + tid] = tanhf(s);
        }
        __syncthreads();

        // ---- GEMM2 partial over my j-slice, all 512 k; 1 k per thread ----
        {
            unsigned long long b01 = 0ull, b23 = 0ull;
            #pragma unroll 16
            for (int j = 0; j < 64; ++j) {
                unsigned long long w2 = pack2(wT_s[j * WSTRIDE + k2]);
                ulonglong2 p = pre2[j];
                ffma2(b01, w2, p.x);
                ffma2(b23, w2, p.y);
            }
            st_dsm_v2(red_dst, b01, b23);   // one 16B DSMEM store
        }
        cluster_sync_();                     // partials visible

        // ---- owner reduce + state update (tid < 256) ----
        if (tid < 256) {
            int tn = (t + 1 < T_LEN) ? (t + 1) : (T_LEN - 1);
            float tI_next = g_tanhI[row_base + (size_t)tn * NH];

            float s = 0.f;
            #pragma unroll
            for (int src = 0; src < 8; ++src) s += sm[RED_OFF + src * 256 + tid];

            hz_r = hz_r + DT_C * (tI - s - g_r * hy_r - e_r * hz_r);
            hy_r = hy_r + DT_C * hz_r;
            tI = tI_next;

            out_states[(size_t)(m_base + m_u) * T_LEN * NH + (size_t)t * NH + k_own] = hy_r;
            sm[HYST_OFF + tid] = hy_r;
        }
        __syncthreads();

        // ---- broadcast new hy slice: each thread one 16B DSMEM store ----
        {
            ulonglong2 hv = *reinterpret_cast<const ulonglong2*>(sm + HYST_OFF + (tid & 63) * 4);
            st_dsm_v2(hy_dst, hv.x, hv.y);
        }
        cluster_sync_();                     // hy visible for next GEMM1
    }

    if (tid < 256 && out_hy)
        out_hy[(size_t)(m_base + m_u) * NH + k_own] = hy_r;
}

// ---------------------------------------------------------------------------
extern "C" void kernel_launch(void* const* d_in, const int* in_sizes, int n_in,
                              void* d_out, int out_size) {
    const float* x    = (const float*)d_in[0];
    const float* x2h  = (const float*)d_in[1];
    const float* h2h  = (const float*)d_in[2];
    const float* bias = (const float*)d_in[3];
    const float* gam  = (const float*)d_in[4];
    const float* eps  = (const float*)d_in[5];
    float* out = (float*)d_out;

    const long long BTH = (long long)BSZ * T_LEN * NH;
    float* states = nullptr;
    float* hyout  = nullptr;
    if ((long long)out_size >= BTH) {
        states = out;
        if ((long long)out_size >= BTH + (long long)BSZ * NH) hyout = out + BTH;
    } else {
        hyout = out;
    }

    phase1_kernel<<<(BSZ * T_LEN) / 16, 256>>>(x, x2h);

    cudaFuncSetAttribute(rnn_kernel, cudaFuncAttributeMaxDynamicSharedMemorySize,
                         SMEM_BYTES);

    cudaLaunchConfig_t cfg = {};
    cfg.gridDim = dim3(128, 1, 1);
    cfg.blockDim = dim3(512, 1, 1);
    cfg.dynamicSmemBytes = SMEM_BYTES;
    cfg.stream = 0;
    cudaLaunchAttribute attrs[1];
    attrs[0].id = cudaLaunchAttributeClusterDimension;
    attrs[0].val.clusterDim.x = 8;
    attrs[0].val.clusterDim.y = 1;
    attrs[0].val.clusterDim.z = 1;
    cfg.attrs = attrs;
    cfg.numAttrs = 1;
    cudaLaunchKernelEx(&cfg, rnn_kernel, h2h, bias, gam, eps, states, hyout);
}